// round 1
// baseline (speedup 1.0000x reference)
#include <cuda_runtime.h>
#include <math.h>

#define BB 16
#define CC 64
#define NN 2000
#define OCC 64
#define NP 2048   // padded size for bitonic sort

// ---------------- scratch (no allocations allowed) ----------------
__device__ float g_h[BB * NN * OCC];          // h[b][n][c]
__device__ float g_f1[BB * NN];
__device__ float g_f2[BB * NN];
__device__ float g_f2s[BB * NP];              // sorted f2 (ascending), padded with +inf
__device__ int   g_perm[BB * NP];             // permutation: sorted rank -> original j
__device__ float g_preH[BB * (NN + 1) * OCC]; // prefix of exp(0.01*f2)*h over sorted order
__device__ float g_sufH[BB * (NN + 1) * OCC]; // suffix of exp(f2)*h over sorted order
__device__ float g_preZ[BB * (NN + 1)];
__device__ float g_sufZ[BB * (NN + 1)];

// ---------------- kernel A: h[b,n,:] = inp[b,:,n]^T @ W ----------------
// grid (25, 16), block 256; tile of 80 n-columns per block
__global__ void k_h(const float* __restrict__ inp, const float* __restrict__ W) {
    __shared__ float xs[80][CC + 1];
    __shared__ float Ws[CC][OCC];
    int b = blockIdx.y;
    int n0 = blockIdx.x * 80;
    int tid = threadIdx.x;

    for (int t = tid; t < CC * OCC; t += 256)
        Ws[t >> 6][t & 63] = W[t];
    for (int t = tid; t < 80 * CC; t += 256) {
        int c = t / 80, nl = t % 80;
        xs[nl][c] = inp[(b * CC + c) * NN + n0 + nl];
    }
    __syncthreads();

    for (int t = tid; t < 80 * OCC; t += 256) {
        int nl = t >> 6, c = t & 63;
        float acc = 0.f;
#pragma unroll
        for (int k = 0; k < CC; k++)
            acc = fmaf(xs[nl][k], Ws[k][c], acc);
        g_h[(b * NN + n0 + nl) * OCC + c] = acc;
    }
}

// ---------------- kernel B: f1 = h@a1, f2 = h@a2 (warp per row) ----------------
__global__ void k_f(const float* __restrict__ a) {
    int row = blockIdx.x * 8 + (threadIdx.x >> 5);   // 0..31999
    int lane = threadIdx.x & 31;
    if (row >= BB * NN) return;
    float h0 = g_h[row * OCC + lane];
    float h1 = g_h[row * OCC + 32 + lane];
    float a10 = a[lane], a11 = a[32 + lane];
    float a20 = a[64 + lane], a21 = a[96 + lane];
    float s1 = h0 * a10 + h1 * a11;
    float s2 = h0 * a20 + h1 * a21;
#pragma unroll
    for (int o = 16; o; o >>= 1) {
        s1 += __shfl_xor_sync(0xffffffffu, s1, o);
        s2 += __shfl_xor_sync(0xffffffffu, s2, o);
    }
    if (lane == 0) { g_f1[row] = s1; g_f2[row] = s2; }
}

// ---------------- kernel C: per-batch bitonic sort of f2 (ascending) ----------------
// grid 16, block 1024, 2048 elements (padded +inf)
__global__ void k_sort() {
    __shared__ float key[NP];
    __shared__ int   idx[NP];
    int b = blockIdx.x, tid = threadIdx.x;

    for (int i = tid; i < NP; i += 1024) {
        key[i] = (i < NN) ? g_f2[b * NN + i] : __int_as_float(0x7f800000);
        idx[i] = i;
    }
    __syncthreads();

    for (int kk = 2; kk <= NP; kk <<= 1) {
        for (int j = kk >> 1; j > 0; j >>= 1) {
            for (int base = 0; base < NP; base += 1024) {
                int i = base + tid;
                int ixj = i ^ j;
                if (ixj > i) {
                    bool up = ((i & kk) == 0);
                    float ki = key[i], kx = key[ixj];
                    bool sw = up ? (ki > kx) : (ki < kx);
                    if (sw) {
                        key[i] = kx; key[ixj] = ki;
                        int t = idx[i]; idx[i] = idx[ixj]; idx[ixj] = t;
                    }
                }
            }
            __syncthreads();
        }
    }
    for (int i = tid; i < NP; i += 1024) {
        g_f2s[b * NP + i] = key[i];
        g_perm[b * NP + i] = idx[i];
    }
}

// ---------------- kernel D: weighted prefix/suffix scans over sorted order ----------------
// grid (16, 2): y=0 forward scan with w=exp(0.01*f2), y=1 backward with w=exp(f2)
// block 64 (one thread per channel)
__global__ void k_scan() {
    __shared__ float w[NN];
    int b = blockIdx.x, dir = blockIdx.y, c = threadIdx.x;

    for (int r = c; r < NN; r += 64) {
        float v = g_f2s[b * NP + r];
        w[r] = dir ? expf(v) : expf(0.01f * v);
    }
    __syncthreads();

    const float* hb = g_h + b * NN * OCC;
    const int*   pb = g_perm + b * NP;

    if (dir == 0) {
        float acc = 0.f, accZ = 0.f;
        g_preH[(b * (NN + 1)) * OCC + c] = 0.f;
        if (c == 0) g_preZ[b * (NN + 1)] = 0.f;
#pragma unroll 4
        for (int r = 0; r < NN; r++) {
            int j = pb[r];
            float wv = w[r];
            acc = fmaf(wv, hb[j * OCC + c], acc);
            g_preH[(b * (NN + 1) + r + 1) * OCC + c] = acc;
            if (c == 0) { accZ += wv; g_preZ[b * (NN + 1) + r + 1] = accZ; }
        }
    } else {
        float acc = 0.f, accZ = 0.f;
        g_sufH[(b * (NN + 1) + NN) * OCC + c] = 0.f;
        if (c == 0) g_sufZ[b * (NN + 1) + NN] = 0.f;
#pragma unroll 4
        for (int r = NN - 1; r >= 0; r--) {
            int j = pb[r];
            float wv = w[r];
            acc = fmaf(wv, hb[j * OCC + c], acc);
            g_sufH[(b * (NN + 1) + r) * OCC + c] = acc;
            if (c == 0) { accZ += wv; g_sufZ[b * (NN + 1) + r] = accZ; }
        }
    }
}

// ---------------- kernel E: combine + relu + transpose-store ----------------
// grid (2000, 16), block 64 (one thread per output channel)
__global__ void k_out(float* __restrict__ out) {
    int b = blockIdx.y, i = blockIdx.x, c = threadIdx.x;
    float f1v = g_f1[b * NN + i];
    float th = -f1v;
    const float* fs = g_f2s + b * NP;

    // lower_bound: first sorted index with f2 >= -f1  (t >= 0 -> "pos" branch)
    int lo = 0, hi = NN;
    while (lo < hi) {
        int mid = (lo + hi) >> 1;
        if (fs[mid] < th) lo = mid + 1; else hi = mid;
    }
    int k = lo;

    float A  = expf(f1v);          // pos-branch row factor
    float aa = expf(0.01f * f1v);  // neg-branch row factor
    int base = b * (NN + 1) + k;
    float num = A * g_sufH[base * OCC + c] + aa * g_preH[base * OCC + c];
    float den = A * g_sufZ[base]           + aa * g_preZ[base];
    float v = num / den;
    out[(b * OCC + c) * NN + i] = fmaxf(v, 0.f);
}

// ---------------- launch ----------------
extern "C" void kernel_launch(void* const* d_in, const int* in_sizes, int n_in,
                              void* d_out, int out_size) {
    const float* inp = (const float*)d_in[0];   // (16, 64, 2000)
    const float* W   = (const float*)d_in[1];   // (64, 64)
    const float* a   = (const float*)d_in[2];   // (128, 1)
    // d_in[3] = GL : provably unused (softmax output strictly positive -> mask no-op)
    float* out = (float*)d_out;                 // (16, 64, 2000)

    k_h   <<<dim3(25, BB), 256>>>(inp, W);
    k_f   <<<(BB * NN + 7) / 8, 256>>>(a);
    k_sort<<<BB, 1024>>>();
    k_scan<<<dim3(BB, 2), 64>>>();
    k_out <<<dim3(NN, BB), 64>>>(out);
}

// round 2
// speedup vs baseline: 5.0667x; 5.0667x over previous
#include <cuda_runtime.h>
#include <math.h>

#define BB 16
#define CC 64
#define NN 2000
#define OCC 64
#define NP 2048   // padded size for bitonic sort
#define TILE 128
#define NT 16     // NT*TILE = 2048 >= NN
#define KP 2048   // prefix index space

// ---------------- scratch (no allocations allowed) ----------------
__device__ float g_h[BB * NN * OCC];      // h[b][n][c]
__device__ float g_f1[BB * NN];
__device__ float g_f2[BB * NN];
__device__ float g_f2s[BB * NP];          // sorted f2 (ascending), padded +inf
__device__ int   g_perm[BB * NP];         // sorted rank -> original j

// within-tile exclusive prefixes (S = weight exp(0.01*f2), B = weight exp(f2))
__device__ float g_preS[BB * KP * OCC];
__device__ float g_preB[BB * KP * OCC];
__device__ float g_preZS[BB * KP];
__device__ float g_preZB[BB * KP];
// per-tile sums
__device__ float g_tsS[BB * NT * OCC];
__device__ float g_tsB[BB * NT * OCC];
__device__ float g_tsZS[BB * NT];
__device__ float g_tsZB[BB * NT];
// exclusive tile offsets, index NT holds the total
__device__ float g_toS[BB * (NT + 1) * OCC];
__device__ float g_toB[BB * (NT + 1) * OCC];
__device__ float g_toZS[BB * (NT + 1)];
__device__ float g_toZB[BB * (NT + 1)];

// ---------------- kernel A: h = x^T W, fused f1/f2 = h@a1, h@a2 ----------------
// grid (25, 16), block 256; 80 n-columns per block
__global__ void k_h(const float* __restrict__ inp, const float* __restrict__ W,
                    const float* __restrict__ a) {
    __shared__ float xs[80][CC + 1];
    __shared__ float Ws[CC][OCC];
    __shared__ float f1p[80], f2p[80];
    int b = blockIdx.y;
    int n0 = blockIdx.x * 80;
    int tid = threadIdx.x;

    for (int t = tid; t < CC * OCC; t += 256)
        Ws[t >> 6][t & 63] = W[t];
    for (int t = tid; t < 80 * CC; t += 256) {
        int c = t / 80, nl = t % 80;
        xs[nl][c] = inp[(b * CC + c) * NN + n0 + nl];
    }
    if (tid < 80) { f1p[tid] = 0.f; f2p[tid] = 0.f; }
    __syncthreads();

    for (int t = tid; t < 80 * OCC; t += 256) {   // 20 full passes, no divergence
        int nl = t >> 6, c = t & 63;
        float acc = 0.f;
#pragma unroll
        for (int k = 0; k < CC; k++)
            acc = fmaf(xs[nl][k], Ws[k][c], acc);
        g_h[(b * NN + n0 + nl) * OCC + c] = acc;
        float s1 = acc * a[c];
        float s2 = acc * a[64 + c];
#pragma unroll
        for (int o = 16; o; o >>= 1) {
            s1 += __shfl_xor_sync(0xffffffffu, s1, o);
            s2 += __shfl_xor_sync(0xffffffffu, s2, o);
        }
        if ((tid & 31) == 0) {   // exactly 2 contributors per nl -> deterministic
            atomicAdd(&f1p[nl], s1);
            atomicAdd(&f2p[nl], s2);
        }
    }
    __syncthreads();
    if (tid < 80) {
        g_f1[b * NN + n0 + tid] = f1p[tid];
        g_f2[b * NN + n0 + tid] = f2p[tid];
    }
}

// ---------------- kernel C: per-batch bitonic sort of f2 (ascending) ----------------
__global__ void k_sort() {
    __shared__ float key[NP];
    __shared__ int   idx[NP];
    int b = blockIdx.x, tid = threadIdx.x;

    for (int i = tid; i < NP; i += 1024) {
        key[i] = (i < NN) ? g_f2[b * NN + i] : __int_as_float(0x7f800000);
        idx[i] = i;
    }
    __syncthreads();

    for (int kk = 2; kk <= NP; kk <<= 1) {
        for (int j = kk >> 1; j > 0; j >>= 1) {
            int i = tid;
            {
                int ixj = i ^ j;
                if (ixj > i) {
                    bool up = ((i & kk) == 0);
                    float ki = key[i], kx = key[ixj];
                    bool sw = up ? (ki > kx) : (ki < kx);
                    if (sw) {
                        key[i] = kx; key[ixj] = ki;
                        int t = idx[i]; idx[i] = idx[ixj]; idx[ixj] = t;
                    }
                }
            }
            i = tid + 1024;
            {
                int ixj = i ^ j;
                if (ixj > i) {
                    bool up = ((i & kk) == 0);
                    float ki = key[i], kx = key[ixj];
                    bool sw = up ? (ki > kx) : (ki < kx);
                    if (sw) {
                        key[i] = kx; key[ixj] = ki;
                        int t = idx[i]; idx[i] = idx[ixj]; idx[ixj] = t;
                    }
                }
            }
            __syncthreads();
        }
    }
    for (int i = tid; i < NP; i += 1024) {
        g_f2s[b * NP + i] = key[i];
        g_perm[b * NP + i] = idx[i];
    }
}

// ---------------- kernel D1: within-tile exclusive prefixes + tile sums ----------------
// grid (NT, BB), block 256
__global__ void k_tile() {
    __shared__ float hs[TILE][OCC];
    __shared__ float wS[TILE], wB[TILE];
    __shared__ int   pidx[TILE];
    int b = blockIdx.y, t = blockIdx.x, tid = threadIdx.x;
    int r0 = t * TILE;

    if (tid < TILE) {
        int gp = r0 + tid;
        if (gp < NN) {
            float f = g_f2s[b * NP + gp];
            wS[tid] = expf(0.01f * f);
            wB[tid] = expf(f);
            pidx[tid] = g_perm[b * NP + gp];
        } else {
            wS[tid] = 0.f; wB[tid] = 0.f; pidx[tid] = 0;
        }
    }
    __syncthreads();
    for (int x = tid; x < TILE * OCC; x += 256) {
        int r = x >> 6, c = x & 63;
        hs[r][c] = g_h[(b * NN + pidx[r]) * OCC + c];
    }
    __syncthreads();

    if (tid < 64) {
        int c = tid;
        float aS = 0.f, aB = 0.f;
#pragma unroll 4
        for (int r = 0; r < TILE; r++) {
            int gi = (b * KP + r0 + r) * OCC + c;
            g_preS[gi] = aS;
            g_preB[gi] = aB;
            float hv = hs[r][c];
            aS = fmaf(wS[r], hv, aS);
            aB = fmaf(wB[r], hv, aB);
        }
        g_tsS[(b * NT + t) * OCC + c] = aS;
        g_tsB[(b * NT + t) * OCC + c] = aB;
    } else if (tid == 64) {
        float zS = 0.f, zB = 0.f;
#pragma unroll 4
        for (int r = 0; r < TILE; r++) {
            g_preZS[b * KP + r0 + r] = zS;
            g_preZB[b * KP + r0 + r] = zB;
            zS += wS[r];
            zB += wB[r];
        }
        g_tsZS[b * NT + t] = zS;
        g_tsZB[b * NT + t] = zB;
    }
}

// ---------------- kernel D2: scan tile sums -> exclusive tile offsets + totals ----------------
// grid (BB), block 160
__global__ void k_to() {
    int b = blockIdx.x, tid = threadIdx.x;
    if (tid < 64) {
        int c = tid;
        float acc = 0.f;
        for (int t = 0; t < NT; t++) {
            g_toS[(b * (NT + 1) + t) * OCC + c] = acc;
            acc += g_tsS[(b * NT + t) * OCC + c];
        }
        g_toS[(b * (NT + 1) + NT) * OCC + c] = acc;
    } else if (tid < 128) {
        int c = tid - 64;
        float acc = 0.f;
        for (int t = 0; t < NT; t++) {
            g_toB[(b * (NT + 1) + t) * OCC + c] = acc;
            acc += g_tsB[(b * NT + t) * OCC + c];
        }
        g_toB[(b * (NT + 1) + NT) * OCC + c] = acc;
    } else if (tid == 128) {
        float acc = 0.f;
        for (int t = 0; t < NT; t++) {
            g_toZS[b * (NT + 1) + t] = acc;
            acc += g_tsZS[b * NT + t];
        }
        g_toZS[b * (NT + 1) + NT] = acc;
    } else if (tid == 129) {
        float acc = 0.f;
        for (int t = 0; t < NT; t++) {
            g_toZB[b * (NT + 1) + t] = acc;
            acc += g_tsZB[b * NT + t];
        }
        g_toZB[b * (NT + 1) + NT] = acc;
    }
}

// ---------------- kernel E: combine + relu + coalesced transpose-store ----------------
// grid (125, 16), block (64, 16): 16 rows i per block
__global__ void k_out(float* __restrict__ out) {
    __shared__ float sm[16][OCC + 1];
    int b = blockIdx.y;
    int i0 = blockIdx.x * 16;
    int c = threadIdx.x, il = threadIdx.y;
    int i = i0 + il;

    float f1v = g_f1[b * NN + i];
    float th = -f1v;
    const float* fs = g_f2s + b * NP;

    int lo = 0, hi = NN;            // lower_bound: first idx with f2 >= -f1
    while (lo < hi) {
        int mid = (lo + hi) >> 1;
        if (fs[mid] < th) lo = mid + 1; else hi = mid;
    }
    int k = lo;
    int t = k >> 7;                 // tile of k (k<=2000 -> t<=15)

    float A  = expf(f1v);
    float aa = expf(0.01f * f1v);

    float pS  = g_toS[(b * (NT + 1) + t) * OCC + c] + g_preS[(b * KP + k) * OCC + c];
    float pB  = g_toB[(b * (NT + 1) + t) * OCC + c] + g_preB[(b * KP + k) * OCC + c];
    float TB  = g_toB[(b * (NT + 1) + NT) * OCC + c];
    float pZS = g_toZS[b * (NT + 1) + t] + g_preZS[b * KP + k];
    float pZB = g_toZB[b * (NT + 1) + t] + g_preZB[b * KP + k];
    float TZB = g_toZB[b * (NT + 1) + NT];

    float num = A * (TB - pB)   + aa * pS;
    float den = A * (TZB - pZB) + aa * pZS;
    sm[il][c] = fmaxf(num / den, 0.f);
    __syncthreads();

    int tid = il * 64 + c;
    int c2 = tid >> 4, i2 = tid & 15;
    out[(b * OCC + c2) * NN + i0 + i2] = sm[i2][c2];
}

// ---------------- launch ----------------
extern "C" void kernel_launch(void* const* d_in, const int* in_sizes, int n_in,
                              void* d_out, int out_size) {
    const float* inp = (const float*)d_in[0];   // (16, 64, 2000)
    const float* W   = (const float*)d_in[1];   // (64, 64)
    const float* a   = (const float*)d_in[2];   // (128, 1)
    // d_in[3] = GL : unused (softmax output strictly positive -> adjacency mask is a no-op)
    float* out = (float*)d_out;                 // (16, 64, 2000)

    k_h   <<<dim3(25, BB), 256>>>(inp, W, a);
    k_sort<<<BB, 1024>>>();
    k_tile<<<dim3(NT, BB), 256>>>();
    k_to  <<<BB, 160>>>();
    k_out <<<dim3(125, BB), dim3(64, 16)>>>(out);
}

// round 3
// speedup vs baseline: 5.7331x; 1.1315x over previous
#include <cuda_runtime.h>
#include <math.h>

#define BB 16
#define CC 64
#define NN 2000
#define OCC 64
#define NP 2048   // padded size for bitonic sort
#define TILE 128
#define NT 16     // NT*TILE = 2048 >= NN
#define KP 2048   // prefix index space

// ---------------- scratch (no allocations allowed) ----------------
__device__ float  g_h[BB * NN * OCC];    // h[b][n][c]
__device__ float  g_f1[BB * NN];
__device__ float  g_f2[BB * NN];
__device__ float  g_f2s[BB * NP];        // sorted f2 (ascending), padded +inf
__device__ int    g_perm[BB * NP];       // sorted rank -> original j
__device__ float2 g_pre[BB * KP * OCC];  // within-tile excl prefix {S=exp(.01 f2)*h, B=exp(f2)*h}
__device__ float2 g_preZ[BB * KP];       // within-tile excl prefix of weights {S,B}
__device__ float2 g_ts[BB * NT * OCC];   // per-tile sums {S,B}
__device__ float2 g_tsZ[BB * NT];        // per-tile weight sums {S,B}

// ---------------- kernel A: h = x^T W ; f1 = x^T (W a1), f2 = x^T (W a2) ----------------
// grid (25, 16), block 256; 80 n-columns per block
__global__ void k_h(const float* __restrict__ inp, const float* __restrict__ W,
                    const float* __restrict__ a) {
    __shared__ float xs[80][CC + 1];
    __shared__ float Ws[CC][OCC + 1];
    __shared__ float as_[128];
    __shared__ float wa1[CC], wa2[CC];
    int b = blockIdx.y;
    int n0 = blockIdx.x * 80;
    int tid = threadIdx.x;

    for (int t = tid; t < CC * OCC; t += 256)
        Ws[t >> 6][t & 63] = W[t];
    for (int t = tid; t < 80 * CC; t += 256) {
        int c = t / 80, nl = t % 80;
        xs[nl][c] = inp[(b * CC + c) * NN + n0 + nl];
    }
    if (tid < 128) as_[tid] = a[tid];
    __syncthreads();

    // wa1 = W @ a1, wa2 = W @ a2 (warps 0-3)
    if (tid < 128) {
        int c = tid & 63;
        const float* av = as_ + (tid >> 6) * 64;
        float s = 0.f;
#pragma unroll
        for (int oc = 0; oc < 64; oc++)
            s = fmaf(Ws[c][oc], av[oc], s);
        if (tid < 64) wa1[c] = s; else wa2[c] = s;
    }

    // main GEMM: 20 full passes per thread
    for (int t = tid; t < 80 * OCC; t += 256) {
        int nl = t >> 6, c = t & 63;
        float acc = 0.f;
#pragma unroll
        for (int k = 0; k < CC; k++)
            acc = fmaf(xs[nl][k], Ws[k][c], acc);
        g_h[(b * NN + n0 + nl) * OCC + c] = acc;
    }
    __syncthreads();

    // f1/f2 straight dot products (no shuffles, no atomics)
    if (tid < 80) {
        float s1 = 0.f, s2 = 0.f;
#pragma unroll
        for (int k = 0; k < CC; k++) {
            float xv = xs[tid][k];
            s1 = fmaf(xv, wa1[k], s1);
            s2 = fmaf(xv, wa2[k], s2);
        }
        g_f1[b * NN + n0 + tid] = s1;
        g_f2[b * NN + n0 + tid] = s2;
    }
}

// ---------------- kernel C: per-batch bitonic sort of f2 (ascending) ----------------
__global__ void k_sort() {
    __shared__ float key[NP];
    __shared__ int   idx[NP];
    int b = blockIdx.x, tid = threadIdx.x;

    for (int i = tid; i < NP; i += 1024) {
        key[i] = (i < NN) ? g_f2[b * NN + i] : __int_as_float(0x7f800000);
        idx[i] = i;
    }
    __syncthreads();

    for (int kk = 2; kk <= NP; kk <<= 1) {
        for (int j = kk >> 1; j > 0; j >>= 1) {
#pragma unroll
            for (int half = 0; half < 2; half++) {
                int i = tid + half * 1024;
                int ixj = i ^ j;
                if (ixj > i) {
                    bool up = ((i & kk) == 0);
                    float ki = key[i], kx = key[ixj];
                    bool sw = up ? (ki > kx) : (ki < kx);
                    if (sw) {
                        key[i] = kx; key[ixj] = ki;
                        int t = idx[i]; idx[i] = idx[ixj]; idx[ixj] = t;
                    }
                }
            }
            __syncthreads();
        }
    }
    for (int i = tid; i < NP; i += 1024) {
        g_f2s[b * NP + i] = key[i];
        g_perm[b * NP + i] = idx[i];
    }
}

// ---------------- kernel D: within-tile exclusive prefixes + tile sums ----------------
// grid (NT, BB), block 256
__global__ void k_tile() {
    __shared__ float hs[TILE][OCC];
    __shared__ float wS[TILE], wB[TILE];
    __shared__ int   pidx[TILE];
    int b = blockIdx.y, t = blockIdx.x, tid = threadIdx.x;
    int r0 = t * TILE;

    if (tid < TILE) {
        int gp = r0 + tid;
        if (gp < NN) {
            float f = g_f2s[b * NP + gp];
            wS[tid] = expf(0.01f * f);
            wB[tid] = expf(f);
            pidx[tid] = g_perm[b * NP + gp];
        } else {
            wS[tid] = 0.f; wB[tid] = 0.f; pidx[tid] = 0;
        }
    }
    __syncthreads();
    // gather h rows (float4, coalesced within rows)
    for (int x = tid; x < TILE * 16; x += 256) {
        int r = x >> 4, q = x & 15;
        reinterpret_cast<float4*>(hs[r])[q] =
            reinterpret_cast<const float4*>(g_h + (size_t)(b * NN + pidx[r]) * OCC)[q];
    }
    __syncthreads();

    if (tid < 64) {
        int c = tid;
        float aS = 0.f, aB = 0.f;
#pragma unroll 4
        for (int r = 0; r < TILE; r++) {
            g_pre[(size_t)(b * KP + r0 + r) * OCC + c] = make_float2(aS, aB);
            float hv = hs[r][c];
            aS = fmaf(wS[r], hv, aS);
            aB = fmaf(wB[r], hv, aB);
        }
        g_ts[(b * NT + t) * OCC + c] = make_float2(aS, aB);
    } else if (tid == 64) {
        float zS = 0.f, zB = 0.f;
#pragma unroll 4
        for (int r = 0; r < TILE; r++) {
            g_preZ[b * KP + r0 + r] = make_float2(zS, zB);
            zS += wS[r];
            zB += wB[r];
        }
        g_tsZ[b * NT + t] = make_float2(zS, zB);
    }
}

// ---------------- kernel E: search + tile-offset prefix + combine + relu + transpose ----------------
// grid (125, 16), block (64, 16)
__global__ void k_out(float* __restrict__ out) {
    __shared__ float fs[NN];
    __shared__ float sm[16][OCC + 1];
    __shared__ int   kks[16];
    __shared__ float f1s[16];
    __shared__ float zpreS[NT + 1], zpreB[NT + 1];
    int b = blockIdx.y;
    int i0 = blockIdx.x * 16;
    int c = threadIdx.x, il = threadIdx.y;
    int tid = il * 64 + c;

    for (int x = tid; x < NN; x += 1024)
        fs[x] = g_f2s[b * NP + x];
    if (tid < 16) f1s[tid] = g_f1[b * NN + i0 + tid];
    __syncthreads();

    if (tid < 16) {
        float th = -f1s[tid];
        int lo = 0, hi = NN;     // lower_bound: first idx with f2 >= -f1
        while (lo < hi) {
            int mid = (lo + hi) >> 1;
            if (fs[mid] < th) lo = mid + 1; else hi = mid;
        }
        kks[tid] = lo;
    } else if (tid == 16) {
        float aS = 0.f, aB = 0.f;
#pragma unroll
        for (int t2 = 0; t2 < NT; t2++) {
            zpreS[t2] = aS; zpreB[t2] = aB;
            float2 z = g_tsZ[b * NT + t2];
            aS += z.x; aB += z.y;
        }
        zpreS[NT] = aS; zpreB[NT] = aB;
    }
    __syncthreads();

    int k = kks[il];
    int t = k >> 7;
    float f1v = f1s[il];
    float A  = expf(f1v);
    float aa = expf(0.01f * f1v);

    // per-channel tile-offset prefix in registers (independent loads, predicated adds)
    float accS = 0.f, accB = 0.f, TB = 0.f;
#pragma unroll
    for (int t2 = 0; t2 < NT; t2++) {
        float2 v = g_ts[(b * NT + t2) * OCC + c];
        if (t2 < t) { accS += v.x; accB += v.y; }
        TB += v.y;
    }
    float2 pre  = g_pre[(size_t)(b * KP + k) * OCC + c];
    float2 preZ = g_preZ[b * KP + k];

    float pS  = accS + pre.x;
    float pB  = accB + pre.y;
    float pZS = zpreS[t] + preZ.x;
    float pZB = zpreB[t] + preZ.y;
    float TZB = zpreB[NT];

    float num = A * (TB - pB)   + aa * pS;
    float den = A * (TZB - pZB) + aa * pZS;
    sm[il][c] = fmaxf(num / den, 0.f);
    __syncthreads();

    int c2 = tid >> 4, i2 = tid & 15;
    out[(b * OCC + c2) * NN + i0 + i2] = sm[i2][c2];
}

// ---------------- launch ----------------
extern "C" void kernel_launch(void* const* d_in, const int* in_sizes, int n_in,
                              void* d_out, int out_size) {
    const float* inp = (const float*)d_in[0];   // (16, 64, 2000)
    const float* W   = (const float*)d_in[1];   // (64, 64)
    const float* a   = (const float*)d_in[2];   // (128, 1)
    // d_in[3] = GL : unused (softmax output strictly positive -> adjacency mask is a no-op)
    float* out = (float*)d_out;                 // (16, 64, 2000)

    k_h   <<<dim3(25, BB), 256>>>(inp, W, a);
    k_sort<<<BB, 1024>>>();
    k_tile<<<dim3(NT, BB), 256>>>();
    k_out <<<dim3(125, BB), dim3(64, 16)>>>(out);
}

// round 4
// speedup vs baseline: 8.0747x; 1.4084x over previous
#include <cuda_runtime.h>
#include <math.h>

#define BB 16
#define CC 64
#define NN 2000
#define OCC 64
#define NP 2048   // padded size for bitonic sort
#define TILE 128
#define NT 16     // NT*TILE = 2048 >= NN
#define KP 2048   // prefix index space

// ---------------- scratch (no allocations allowed) ----------------
__device__ float  g_h[BB * NN * OCC];    // h[b][n][c]
__device__ float  g_f1[BB * NN];
__device__ float  g_f2[BB * NN];
__device__ float  g_f2s[BB * NP];        // sorted f2 (ascending), padded +inf
__device__ int    g_perm[BB * NP];       // sorted rank -> original j
__device__ float2 g_pre[BB * KP * OCC];  // within-tile excl prefix {S=exp(.01 f2)*h, B=exp(f2)*h}
__device__ float2 g_preZ[BB * KP];       // within-tile excl prefix of weights {S,B}
__device__ float2 g_ts[BB * NT * OCC];   // per-tile sums {S,B}
__device__ float2 g_tsZ[BB * NT];        // per-tile weight sums {S,B}

// ---------------- kernel A: h = x^T W ; f1 = x^T (W a1), f2 = x^T (W a2) ----------------
// grid (25, 16), block 256; 80 n-columns per block
__global__ void k_h(const float* __restrict__ inp, const float* __restrict__ W,
                    const float* __restrict__ a) {
    __shared__ float xs[80][CC + 1];
    __shared__ float Ws[CC][OCC + 1];
    __shared__ float as_[128];
    __shared__ float wa1[CC], wa2[CC];
    int b = blockIdx.y;
    int n0 = blockIdx.x * 80;
    int tid = threadIdx.x;

    for (int t = tid; t < CC * OCC; t += 256)
        Ws[t >> 6][t & 63] = W[t];
    for (int t = tid; t < 80 * CC; t += 256) {
        int c = t / 80, nl = t % 80;
        xs[nl][c] = inp[(b * CC + c) * NN + n0 + nl];
    }
    if (tid < 128) as_[tid] = a[tid];
    __syncthreads();

    // wa1 = W @ a1, wa2 = W @ a2 (warps 0-3)
    if (tid < 128) {
        int c = tid & 63;
        const float* av = as_ + (tid >> 6) * 64;
        float s = 0.f;
#pragma unroll
        for (int oc = 0; oc < 64; oc++)
            s = fmaf(Ws[c][oc], av[oc], s);
        if (tid < 64) wa1[c] = s; else wa2[c] = s;
    }

    // main GEMM: 20 full passes per thread
    for (int t = tid; t < 80 * OCC; t += 256) {
        int nl = t >> 6, c = t & 63;
        float acc = 0.f;
#pragma unroll
        for (int k = 0; k < CC; k++)
            acc = fmaf(xs[nl][k], Ws[k][c], acc);
        g_h[(b * NN + n0 + nl) * OCC + c] = acc;
    }
    __syncthreads();

    // f1/f2 straight dot products (no shuffles, no atomics)
    if (tid < 80) {
        float s1 = 0.f, s2 = 0.f;
#pragma unroll
        for (int k = 0; k < CC; k++) {
            float xv = xs[tid][k];
            s1 = fmaf(xv, wa1[k], s1);
            s2 = fmaf(xv, wa2[k], s2);
        }
        g_f1[b * NN + n0 + tid] = s1;
        g_f2[b * NN + n0 + tid] = s2;
    }
}

// ---------------- kernel C: per-batch bitonic sort of f2 (ascending) ----------------
__global__ void k_sort() {
    __shared__ float key[NP];
    __shared__ int   idx[NP];
    int b = blockIdx.x, tid = threadIdx.x;

    for (int i = tid; i < NP; i += 1024) {
        key[i] = (i < NN) ? g_f2[b * NN + i] : __int_as_float(0x7f800000);
        idx[i] = i;
    }
    __syncthreads();

    for (int kk = 2; kk <= NP; kk <<= 1) {
        for (int j = kk >> 1; j > 0; j >>= 1) {
#pragma unroll
            for (int half = 0; half < 2; half++) {
                int i = tid + half * 1024;
                int ixj = i ^ j;
                if (ixj > i) {
                    bool up = ((i & kk) == 0);
                    float ki = key[i], kx = key[ixj];
                    bool sw = up ? (ki > kx) : (ki < kx);
                    if (sw) {
                        key[i] = kx; key[ixj] = ki;
                        int t = idx[i]; idx[i] = idx[ixj]; idx[ixj] = t;
                    }
                }
            }
            __syncthreads();
        }
    }
    for (int i = tid; i < NP; i += 1024) {
        g_f2s[b * NP + i] = key[i];
        g_perm[b * NP + i] = idx[i];
    }
}

// ---------------- kernel D: within-tile exclusive prefixes + tile sums ----------------
// grid (NT, BB), block 256
__global__ void k_tile() {
    __shared__ float hs[TILE][OCC];
    __shared__ float wS[TILE], wB[TILE];
    __shared__ int   pidx[TILE];
    int b = blockIdx.y, t = blockIdx.x, tid = threadIdx.x;
    int r0 = t * TILE;

    if (tid < TILE) {
        int gp = r0 + tid;
        if (gp < NN) {
            float f = g_f2s[b * NP + gp];
            wS[tid] = expf(0.01f * f);
            wB[tid] = expf(f);
            pidx[tid] = g_perm[b * NP + gp];
        } else {
            wS[tid] = 0.f; wB[tid] = 0.f; pidx[tid] = 0;
        }
    }
    __syncthreads();
    // gather h rows (float4, coalesced within rows)
    for (int x = tid; x < TILE * 16; x += 256) {
        int r = x >> 4, q = x & 15;
        reinterpret_cast<float4*>(hs[r])[q] =
            reinterpret_cast<const float4*>(g_h + (size_t)(b * NN + pidx[r]) * OCC)[q];
    }
    __syncthreads();

    if (tid < 64) {
        int c = tid;
        float aS = 0.f, aB = 0.f;
#pragma unroll 4
        for (int r = 0; r < TILE; r++) {
            g_pre[(size_t)(b * KP + r0 + r) * OCC + c] = make_float2(aS, aB);
            float hv = hs[r][c];
            aS = fmaf(wS[r], hv, aS);
            aB = fmaf(wB[r], hv, aB);
        }
        g_ts[(b * NT + t) * OCC + c] = make_float2(aS, aB);
    } else if (tid == 64) {
        float zS = 0.f, zB = 0.f;
#pragma unroll 4
        for (int r = 0; r < TILE; r++) {
            g_preZ[b * KP + r0 + r] = make_float2(zS, zB);
            zS += wS[r];
            zB += wB[r];
        }
        g_tsZ[b * NT + t] = make_float2(zS, zB);
    }
}

// ---------------- kernel E: search + combine + relu + transpose (80 rows / block) ----------------
// grid (25, 16), block (64, 16)
__global__ void k_out(float* __restrict__ out) {
    __shared__ float  fs[NN];              // sorted f2, staged once per 80 rows
    __shared__ float  sm[80][OCC + 1];     // results before transpose-store
    __shared__ float2 to[NT + 1][OCC];     // per-channel exclusive tile offsets (+ total)
    __shared__ float  zpreS[NT + 1], zpreB[NT + 1];
    __shared__ int    kks[80];
    __shared__ float  f1s[80];

    int b = blockIdx.y;
    int i0 = blockIdx.x * 80;
    int c = threadIdx.x, il = threadIdx.y;
    int tid = il * 64 + c;

    for (int x = tid; x < NN; x += 1024)
        fs[x] = g_f2s[b * NP + x];
    if (tid < 80) f1s[tid] = g_f1[b * NN + i0 + tid];

    // per-channel tile-offset prefix: 64 threads, 16 independent loads each
    if (tid >= 128 && tid < 192) {
        int ch = tid - 128;
        float aS = 0.f, aB = 0.f;
#pragma unroll
        for (int t2 = 0; t2 < NT; t2++) {
            to[t2][ch] = make_float2(aS, aB);
            float2 v = g_ts[(b * NT + t2) * OCC + ch];
            aS += v.x; aB += v.y;
        }
        to[NT][ch] = make_float2(aS, aB);
    } else if (tid == 192) {
        float aS = 0.f, aB = 0.f;
#pragma unroll
        for (int t2 = 0; t2 < NT; t2++) {
            zpreS[t2] = aS; zpreB[t2] = aB;
            float2 z = g_tsZ[b * NT + t2];
            aS += z.x; aB += z.y;
        }
        zpreS[NT] = aS; zpreB[NT] = aB;
    }
    __syncthreads();

    if (tid < 80) {
        float th = -f1s[tid];
        int lo = 0, hi = NN;     // lower_bound: first idx with f2 >= -f1
        while (lo < hi) {
            int mid = (lo + hi) >> 1;
            if (fs[mid] < th) lo = mid + 1; else hi = mid;
        }
        kks[tid] = lo;
    }
    __syncthreads();

    // 5 passes x 16 rows: combine
#pragma unroll
    for (int g = 0; g < 5; g++) {
        int rl = g * 16 + il;               // local row 0..79
        int k = kks[rl];
        int t = k >> 7;
        float f1v = f1s[rl];
        float A  = expf(f1v);
        float aa = expf(0.01f * f1v);

        float2 pre  = g_pre[(size_t)(b * KP + k) * OCC + c];
        float2 preZ = g_preZ[b * KP + k];
        float2 tov  = to[t][c];
        float2 tot  = to[NT][c];

        float pS  = tov.x + pre.x;
        float pB  = tov.y + pre.y;
        float pZS = zpreS[t] + preZ.x;
        float pZB = zpreB[t] + preZ.y;

        float num = A * (tot.y - pB)      + aa * pS;
        float den = A * (zpreB[NT] - pZB) + aa * pZS;
        sm[rl][c] = fmaxf(num / den, 0.f);
    }
    __syncthreads();

    // transpose-store: 5120 elements, 5 per thread, contiguous i per channel
#pragma unroll
    for (int e = tid; e < OCC * 80; e += 1024) {
        int c2 = e / 80, i2 = e % 80;
        out[(b * OCC + c2) * NN + i0 + i2] = sm[i2][c2];
    }
}

// ---------------- launch ----------------
extern "C" void kernel_launch(void* const* d_in, const int* in_sizes, int n_in,
                              void* d_out, int out_size) {
    const float* inp = (const float*)d_in[0];   // (16, 64, 2000)
    const float* W   = (const float*)d_in[1];   // (64, 64)
    const float* a   = (const float*)d_in[2];   // (128, 1)
    // d_in[3] = GL : unused (softmax output strictly positive -> adjacency mask is a no-op)
    float* out = (float*)d_out;                 // (16, 64, 2000)

    k_h   <<<dim3(25, BB), 256>>>(inp, W, a);
    k_sort<<<BB, 1024>>>();
    k_tile<<<dim3(NT, BB), 256>>>();
    k_out <<<dim3(25, BB), dim3(64, 16)>>>(out);
}